// round 8
// baseline (speedup 1.0000x reference)
#include <cuda_runtime.h>
#include <cstdint>

// RWKV7 chunked attention, B=4 T=2048 H=32 C=64 dT=16.
// One CTA (512 thr) per (b,h). Software pipeline:
//   producer warps 8-15: chunk ch+1 stage + grams + AKV/QKV + ACCV (state-independent)
//   consumer warps 0-7 : chunk ch   state GEMM + solve + y + state update
// Double-buffered smem handoff, named barriers per group, 1 syncthreads/chunk.

#define B_ 4
#define T_ 2048
#define H_ 32
#define C_ 64
#define DT_ 16
#define NT_ 128
#define THREADS 512

typedef unsigned long long u64;

// ---- shared layout (float words) ----
#define OFF_S    0          // [64][64] sg swizzle
#define OFF_U    4096       // [16][64] tg swizzle
#define OFF_ABU  5120       // [16][64]
#define OFF_AKQK 6144       // [16][16] (ak,qk) pairs, producer-local
#define OFF_LPP  6656       // [4][64] producer prefix scratch
#define OFF_BUF  6912
#define BUF_STRIDE 7744
// offsets within one buffer:
#define BWA  0
#define BWQ  1024
#define BKWI 2048
#define BBWI 3072
#define BV   4096
#define BAKV 5120
#define BQKV 6144
#define BAB  7168
#define BQB  7424
#define BFW  7680
#define OFF_ACCV (OFF_BUF + 2 * BUF_STRIDE)      // 2 x [64][64] sg swizzle
#define SMEM_WORDS (OFF_ACCV + 2 * 4096)         // 30592 floats = 122.4 KB
#define SMEM_BYTES (SMEM_WORDS * 4)

#define BARC() asm volatile("bar.sync 1, 256;" ::: "memory")   // consumer group
#define BARP() asm volatile("bar.sync 2, 256;" ::: "memory")   // producer group

// xor swizzles
__device__ __forceinline__ int tg(int t, int f)  { return t * 64 + (((f ^ t) & 15) << 2); }
__device__ __forceinline__ int tw(int t, int c)  { return t * 64 + ((((c >> 2) ^ t) & 15) << 2) + (c & 3); }
__device__ __forceinline__ int sg(int r, int f)  { return r * 64 + (((f ^ (r >> 2)) & 15) << 2); }

__device__ __forceinline__ float4 ld4(const float* p) { return *reinterpret_cast<const float4*>(p); }
__device__ __forceinline__ void st4(float* p, float4 v) { *reinterpret_cast<float4*>(p) = v; }
__device__ __forceinline__ ulonglong2 ldp(const float* p) { return *reinterpret_cast<const ulonglong2*>(p); }
__device__ __forceinline__ void stp(float* p, ulonglong2 v) { *reinterpret_cast<ulonglong2*>(p) = v; }

__device__ __forceinline__ u64 pk2(float lo, float hi) {
    u64 r; asm("mov.b64 %0, {%1, %2};" : "=l"(r) : "f"(lo), "f"(hi)); return r;
}
__device__ __forceinline__ void un2(u64 v, float& lo, float& hi) {
    asm("mov.b64 {%0, %1}, %2;" : "=f"(lo), "=f"(hi) : "l"(v));
}
__device__ __forceinline__ void fma2(u64& d, u64 a, u64 b) {
    asm("fma.rn.f32x2 %0, %1, %2, %0;" : "+l"(d) : "l"(a), "l"(b));
}
__device__ __forceinline__ u64 add2(u64 a, u64 b) {
    u64 d; asm("add.rn.f32x2 %0, %1, %2;" : "=l"(d) : "l"(a), "l"(b)); return d;
}
__device__ __forceinline__ u64 mul2(u64 a, u64 b) {
    u64 d; asm("mul.rn.f32x2 %0, %1, %2;" : "=l"(d) : "l"(a), "l"(b)); return d;
}

// ---------- producer: stage chunk cp into buffer buf, accv into av ----------
__device__ __forceinline__ void produce(
    float* __restrict__ sm, float* __restrict__ buf, float* __restrict__ av,
    const float* __restrict__ gw, const float* __restrict__ gq,
    const float* __restrict__ gk, const float* __restrict__ gv,
    const float* __restrict__ ga, const float* __restrict__ gb,
    int b, int h, int cp, int pt)
{
    const int th = pt >> 6;        // 0..3, owns t = 4*th + r
    const int cl = pt & 63;
    const size_t strT = (size_t)H_ * C_;

    // load + decay + stage
    {
        size_t base = (((size_t)b * T_ + cp * DT_ + 4 * th) * H_ + h) * C_ + cl;
        float rw[4], rq[4], rk[4], rv[4], ra[4], rb[4];
        #pragma unroll
        for (int r = 0; r < 4; r++) {
            size_t ix = base + (size_t)r * strT;
            rw[r] = gw[ix]; rq[r] = gq[ix]; rk[r] = gk[ix];
            rv[r] = gv[ix]; ra[r] = ga[ix]; rb[r] = gb[ix];
        }
        float wd[4]; float lp = 1.f;
        #pragma unroll
        for (int r = 0; r < 4; r++) { wd[r] = __expf(-__expf(rw[r])); lp *= wd[r]; }
        sm[OFF_LPP + th * 64 + cl] = lp;
        BARP();
        float incl = 1.f;
        #pragma unroll
        for (int gg = 0; gg < 3; gg++)
            if (gg < th) incl *= sm[OFF_LPP + gg * 64 + cl];
        #pragma unroll
        for (int r = 0; r < 4; r++) {
            int t = 4 * th + r;
            float ip = incl; incl *= wd[r];
            float rinv = __fdividef(1.f, incl);
            int twd = tw(t, cl);
            buf[BWQ  + twd] = rq[r] * incl;
            buf[BWA  + twd] = ra[r] * ip;
            buf[BKWI + twd] = rk[r] * rinv;
            buf[BBWI + twd] = rb[r] * rinv;
            buf[BV   + twd] = rv[r];
        }
        if (th == 3) buf[BFW + cl] = incl;
    }
    BARP();

    // grams: (t, s) one thread each
    {
        const int t = pt >> 4, s = pt & 15;
        u64 ab2 = 0, ak2 = 0, qb2 = 0, qk2 = 0;
        #pragma unroll
        for (int c4 = 0; c4 < 16; c4++) {
            ulonglong2 A  = ldp(buf + BWA  + tg(t, c4));
            ulonglong2 Q  = ldp(buf + BWQ  + tg(t, c4));
            ulonglong2 Bv = ldp(buf + BBWI + tg(s, c4));
            ulonglong2 Kv = ldp(buf + BKWI + tg(s, c4));
            fma2(ab2, A.x, Bv.x); fma2(ab2, A.y, Bv.y);
            fma2(ak2, A.x, Kv.x); fma2(ak2, A.y, Kv.y);
            fma2(qb2, Q.x, Bv.x); fma2(qb2, Q.y, Bv.y);
            fma2(qk2, Q.x, Kv.x); fma2(qk2, Q.y, Kv.y);
        }
        float l, hh, ab, ak, qb, qk;
        un2(ab2, l, hh); ab = l + hh;
        un2(ak2, l, hh); ak = l + hh;
        un2(qb2, l, hh); qb = l + hh;
        un2(qk2, l, hh); qk = l + hh;
        float ms = (t > s)  ? 1.f : 0.f;
        float mi = (t >= s) ? 1.f : 0.f;
        buf[BAB + t * 16 + s] = ab * ms;
        buf[BQB + t * 16 + s] = qb * mi;
        *reinterpret_cast<u64*>(sm + OFF_AKQK + (t * 16 + s) * 2) = pk2(ak * ms, qk * mi);
    }
    BARP();

    // AKV = ak@v, QKV = qk@v
    {
        const int t = pt >> 4, iq = pt & 15;
        u64 acc[4] = {0, 0, 0, 0};
        #pragma unroll
        for (int s = 0; s < 16; s++) {
            u64 akqk = *reinterpret_cast<const u64*>(sm + OFF_AKQK + (t * 16 + s) * 2);
            float4 v4 = ld4(buf + BV + tg(s, iq));
            fma2(acc[0], akqk, pk2(v4.x, v4.x));
            fma2(acc[1], akqk, pk2(v4.y, v4.y));
            fma2(acc[2], akqk, pk2(v4.z, v4.z));
            fma2(acc[3], akqk, pk2(v4.w, v4.w));
        }
        float akv[4], qkv[4];
        #pragma unroll
        for (int r = 0; r < 4; r++) un2(acc[r], akv[r], qkv[r]);
        st4(buf + BAKV + tg(t, iq), make_float4(akv[0], akv[1], akv[2], akv[3]));
        st4(buf + BQKV + tg(t, iq), make_float4(qkv[0], qkv[1], qkv[2], qkv[3]));
    }

    // ACCV = v^T kwi (moved off the consumer) -> av
    {
        const int iq2 = pt >> 4, jq = pt & 15;
        u64 acc[4][2];
        #pragma unroll
        for (int r = 0; r < 4; r++) { acc[r][0] = 0; acc[r][1] = 0; }
        #pragma unroll
        for (int t = 0; t < DT_; t++) {
            float4 v4 = ld4(buf + BV + tg(t, iq2));
            ulonglong2 K2 = ldp(buf + BKWI + tg(t, jq));
            u64 v0 = pk2(v4.x, v4.x), v1 = pk2(v4.y, v4.y);
            u64 v2 = pk2(v4.z, v4.z), v3 = pk2(v4.w, v4.w);
            fma2(acc[0][0], v0, K2.x); fma2(acc[0][1], v0, K2.y);
            fma2(acc[1][0], v1, K2.x); fma2(acc[1][1], v1, K2.y);
            fma2(acc[2][0], v2, K2.x); fma2(acc[2][1], v2, K2.y);
            fma2(acc[3][0], v3, K2.x); fma2(acc[3][1], v3, K2.y);
        }
        #pragma unroll
        for (int r = 0; r < 4; r++) {
            ulonglong2 o; o.x = acc[r][0]; o.y = acc[r][1];
            stp(av + sg(4 * iq2 + r, jq), o);
        }
    }
}

__global__ __launch_bounds__(THREADS, 1)
void rwkv7_kernel(const float* __restrict__ gw, const float* __restrict__ gq,
                  const float* __restrict__ gk, const float* __restrict__ gv,
                  const float* __restrict__ ga, const float* __restrict__ gb,
                  const float* __restrict__ gs0, float* __restrict__ gy)
{
    extern __shared__ float sm[];

    const int bh  = blockIdx.x;
    const int b   = bh / H_;
    const int h   = bh % H_;
    const int tid = threadIdx.x;
    const bool is_prod = tid >= 256;
    const int pt = tid & 255;

    // consumer GEMM/y mapping: warp covers 4 t x 8 i-quads
    const int w   = pt >> 5;
    const int tx  = (w & 3) * 4 + ((pt >> 3) & 3);
    const int iq  = ((w >> 2) & 1) * 8 + (pt & 7);
    // consumer update mapping
    const int iq2 = pt >> 4;
    const int jq  = pt & 15;

    // ---- bootstrap ----
    if (is_prod) {
        produce(sm, sm + OFF_BUF, sm + OFF_ACCV, gw, gq, gk, gv, ga, gb, b, h, 0, pt);
    } else {
        const float* s0p = gs0 + (size_t)bh * 4096;
        #pragma unroll
        for (int q4 = pt; q4 < 1024; q4 += 256) {
            int row = q4 >> 4, f = q4 & 15;
            st4(sm + OFF_S + sg(row, f), ld4(s0p + row * 64 + f * 4));
        }
    }
    __syncthreads();

    for (int ch = 0; ch < NT_; ch++) {
        const int p = ch & 1;

        if (is_prod) {
            if (ch + 1 < NT_)
                produce(sm, sm + OFF_BUF + (p ^ 1) * BUF_STRIDE,
                        sm + OFF_ACCV + (p ^ 1) * 4096,
                        gw, gq, gk, gv, ga, gb, b, h, ch + 1, pt);
        } else {
            float* buf = sm + OFF_BUF + p * BUF_STRIDE;
            float* av  = sm + OFF_ACCV + p * 4096;

            // ===== state GEMM: aa = wa@S^T, ay = wq@S^T =====
            float yp[4];
            {
                u64 aa2[4] = {0,0,0,0}, ay2[4] = {0,0,0,0};
                #pragma unroll
                for (int j4 = 0; j4 < 16; j4++) {
                    ulonglong2 A = ldp(buf + BWA + tg(tx, j4));
                    ulonglong2 Q = ldp(buf + BWQ + tg(tx, j4));
                    #pragma unroll
                    for (int r = 0; r < 4; r++) {
                        ulonglong2 S = ldp(sm + OFF_S + sg(4 * iq + r, j4));
                        fma2(aa2[r], A.x, S.x); fma2(aa2[r], A.y, S.y);
                        fma2(ay2[r], Q.x, S.x); fma2(ay2[r], Q.y, S.y);
                    }
                }
                float4 akv4 = ld4(buf + BAKV + tg(tx, iq));
                float4 qkv4 = ld4(buf + BQKV + tg(tx, iq));
                float abu[4];
                float l0, h0, l1, h1;
                un2(aa2[0], l0, h0); un2(ay2[0], l1, h1);
                abu[0] = l0 + h0 + akv4.x; yp[0] = l1 + h1 + qkv4.x;
                un2(aa2[1], l0, h0); un2(ay2[1], l1, h1);
                abu[1] = l0 + h0 + akv4.y; yp[1] = l1 + h1 + qkv4.y;
                un2(aa2[2], l0, h0); un2(ay2[2], l1, h1);
                abu[2] = l0 + h0 + akv4.z; yp[2] = l1 + h1 + qkv4.z;
                un2(aa2[3], l0, h0); un2(ay2[3], l1, h1);
                abu[3] = l0 + h0 + akv4.w; yp[3] = l1 + h1 + qkv4.w;
                st4(sm + OFF_ABU + tg(tx, iq),
                    make_float4(abu[0], abu[1], abu[2], abu[3]));
            }
            BARC();   // abu complete

            // ===== solve (I-ab) u = abu (64 columns, 2 warps) =====
            if (pt < 64) {
                const int c = pt;
                float uu[DT_];
                #pragma unroll
                for (int t = 0; t < DT_; t++) uu[t] = sm[OFF_ABU + tw(t, c)];
                #pragma unroll
                for (int t = 1; t < DT_; t++) {
                    float a0 = uu[t], a1 = 0.f, a2 = 0.f, a3 = 0.f;
                    const float* abr = buf + BAB + t * 16;
                    #pragma unroll
                    for (int s4 = 0; 4 * s4 < t; s4++) {
                        float4 abq = ld4(abr + 4 * s4);
                        int s = 4 * s4;
                        if (s     < t) a0 += abq.x * uu[s];
                        if (s + 1 < t) a1 += abq.y * uu[s + 1];
                        if (s + 2 < t) a2 += abq.z * uu[s + 2];
                        if (s + 3 < t) a3 += abq.w * uu[s + 3];
                    }
                    uu[t] = (a0 + a1) + (a2 + a3);
                }
                #pragma unroll
                for (int t = 0; t < DT_; t++) sm[OFF_U + tw(t, c)] = uu[t];
            }
            BARC();   // u ready

            // ===== y = yp + qb@u =====
            {
                float4 qbr[4];
                #pragma unroll
                for (int r = 0; r < 4; r++) qbr[r] = ld4(buf + BQB + tx * 16 + 4 * r);
                u64 y01 = pk2(yp[0], yp[1]);
                u64 y23 = pk2(yp[2], yp[3]);
                #pragma unroll
                for (int s = 0; s < 16; s++) {
                    float qbs = (s & 2) ? ((s & 1) ? qbr[s >> 2].w : qbr[s >> 2].z)
                                        : ((s & 1) ? qbr[s >> 2].y : qbr[s >> 2].x);
                    ulonglong2 U2 = ldp(sm + OFF_U + tg(s, iq));
                    u64 q2 = pk2(qbs, qbs);
                    fma2(y01, q2, U2.x);
                    fma2(y23, q2, U2.y);
                }
                float o0, o1, o2, o3;
                un2(y01, o0, o1); un2(y23, o2, o3);
                size_t yb = (((size_t)b * T_ + ch * DT_ + tx) * H_ + h) * C_ + 4 * iq;
                __stcs(reinterpret_cast<float4*>(gy + yb), make_float4(o0, o1, o2, o3));
            }

            // ===== state update: S = (S + accv(from producer) + u^T bwi) * fw =====
            {
                u64 accR[4][2];
                #pragma unroll
                for (int r = 0; r < 4; r++) {
                    ulonglong2 A0 = ldp(av + sg(4 * iq2 + r, jq));
                    accR[r][0] = A0.x; accR[r][1] = A0.y;
                }
                #pragma unroll
                for (int t = 0; t < DT_; t++) {
                    float4 u4 = ld4(sm + OFF_U + tg(t, iq2));
                    ulonglong2 B2 = ldp(buf + BBWI + tg(t, jq));
                    u64 u0 = pk2(u4.x, u4.x), u1 = pk2(u4.y, u4.y);
                    u64 u2 = pk2(u4.z, u4.z), u3 = pk2(u4.w, u4.w);
                    fma2(accR[0][0], u0, B2.x); fma2(accR[0][1], u0, B2.y);
                    fma2(accR[1][0], u1, B2.x); fma2(accR[1][1], u1, B2.y);
                    fma2(accR[2][0], u2, B2.x); fma2(accR[2][1], u2, B2.y);
                    fma2(accR[3][0], u3, B2.x); fma2(accR[3][1], u3, B2.y);
                }
                ulonglong2 FWp = ldp(buf + BFW + 4 * jq);
                #pragma unroll
                for (int r = 0; r < 4; r++) {
                    float* sp = sm + OFF_S + sg(4 * iq2 + r, jq);
                    ulonglong2 S = ldp(sp);
                    S.x = mul2(add2(S.x, accR[r][0]), FWp.x);
                    S.y = mul2(add2(S.y, accR[r][1]), FWp.y);
                    stp(sp, S);
                }
            }
        }
        __syncthreads();   // buffer handoff
    }
}

extern "C" void kernel_launch(void* const* d_in, const int* in_sizes, int n_in,
                              void* d_out, int out_size)
{
    const float* w  = (const float*)d_in[0];
    const float* q  = (const float*)d_in[1];
    const float* k  = (const float*)d_in[2];
    const float* v  = (const float*)d_in[3];
    const float* a  = (const float*)d_in[4];
    const float* b  = (const float*)d_in[5];
    const float* s0 = (const float*)d_in[6];
    float* y = (float*)d_out;

    cudaFuncSetAttribute(rwkv7_kernel, cudaFuncAttributeMaxDynamicSharedMemorySize, SMEM_BYTES);
    rwkv7_kernel<<<B_ * H_, THREADS, SMEM_BYTES>>>(w, q, k, v, a, b, s0, y);
}